// round 15
// baseline (speedup 1.0000x reference)
#include <cuda_runtime.h>
#include <math.h>
#include <stdint.h>

// Problem shape (fixed by the dataset instance)
#define BATCH 16
#define HEADS 8
#define HDIM  128
#define BSIZE 16                   // tokens per cache block
#define BPS   128                  // blocks per sequence
#define TMAX  2048
#define NSPLIT 32
#define TOK_CTA (TMAX / NSPLIT)    // 64 tokens per CTA
#define BLK_CTA (TOK_CTA / BSIZE)  // 4 cache blocks per CTA
#define THREADS 256
#define NWARPS  8
#define STAGE_T 2                  // tokens per pipeline stage (8KB)
#define NSTAGE  (TOK_CTA / STAGE_T)// 32 stages per phase
#define RING    5                  // 5 x 8KB = 40KB dynamic smem
#define TOKF    (HEADS * HDIM)     // floats per full token row (all heads) = 1024
#define STAGEF  (STAGE_T * TOKF)   // 2048 floats = 8KB

// split-KV partials + per-batch completion counters (zero-init scratch)
__device__ float g_part_o[BATCH * HEADS * NSPLIT * HDIM];
__device__ float g_part_m[BATCH * HEADS * NSPLIT];
__device__ float g_part_l[BATCH * HEADS * NSPLIT];
__device__ unsigned int g_cnt[BATCH];

__device__ __forceinline__ float warp_sum(float v) {
#pragma unroll
    for (int o = 16; o > 0; o >>= 1) v += __shfl_xor_sync(0xffffffffu, v, o);
    return v;
}

// Prefetch one 2-token stage (8KB, all heads, contiguous rows) via cp.async.cg.
// 512 chunks of 16B; 256 threads -> 2 chunks each, fully coalesced 4KB runs.
__device__ __forceinline__ void prefetch_stage(
    float* sb, int s, int tbase, int tid, int last,
    const int* s_bt, const float* cache, const float* fresh)
{
#pragma unroll
    for (int j = 0; j < 2; j++) {
        const int c   = j * THREADS + tid;   // 0..511
        const int tis = c >> 8;              // token in stage (0..1)
        const int ci  = c & 255;             // 16B chunk within 4KB token row
        const int lt  = s * STAGE_T + tis;
        const int t   = tbase + lt;
        const int blk = s_bt[lt >> 4];
        const float* src = (t == last)
            ? (fresh + (size_t)ci * 4)       // fresh row is contiguous [8x128]
            : (cache + (size_t)(blk * BSIZE + (t & (BSIZE - 1))) * TOKF
                     + (size_t)ci * 4);
        const uint32_t dst = (uint32_t)__cvta_generic_to_shared(
                                 sb + (size_t)tis * TOKF + (size_t)ci * 4);
        asm volatile("cp.async.cg.shared.global [%0], [%1], 16;\n"
                     :: "r"(dst), "l"(src));
    }
}

__global__ __launch_bounds__(THREADS)
void paged_attn_split_kernel(const float* __restrict__ q,
                             const float* __restrict__ knew,
                             const float* __restrict__ vnew,
                             const float* __restrict__ kcache,
                             const float* __restrict__ vcache,
                             const int*   __restrict__ block_tables,
                             const int*   __restrict__ context_lens,
                             float*       __restrict__ out)
{
    const float SCALE = 0.08838834764831845f;

    const int idx   = blockIdx.x;
    const int split = idx % NSPLIT;
    const int b     = idx / NSPLIT;
    const int tid   = threadIdx.x;
    const int lane  = tid & 31;
    const int w     = tid >> 5;             // warp w owns head w
    const int tbase = split * TOK_CTA;

    extern __shared__ float s_ring[];       // RING * STAGEF floats = 40KB

    __shared__ int   s_bt[BLK_CTA];
    __shared__ float s_scores[NWARPS][TOK_CTA];   // 2KB
    __shared__ unsigned int s_last;

    if (tid < BLK_CTA)
        s_bt[tid] = block_tables[b * BPS + split * BLK_CTA + tid];

    const int ctx  = context_lens[b];
    const int last = ctx - 1;

    float4 q4 = reinterpret_cast<const float4*>(
                    q + (size_t)(b * HEADS + w) * HDIM)[lane];
    q4.x *= SCALE; q4.y *= SCALE; q4.z *= SCALE; q4.w *= SCALE;

    const float* kfresh = knew + (size_t)b * HEADS * HDIM;
    const float* vfresh = vnew + (size_t)b * HEADS * HDIM;

    __syncthreads();   // s_bt ready before first prefetch

    // ---- prologue: commit stages 0..RING-2 ---------------------------------
#pragma unroll
    for (int s = 0; s < RING - 1; s++) {
        prefetch_stage(s_ring + (size_t)s * STAGEF, s, tbase, tid, last,
                       s_bt, kcache, kfresh);
        asm volatile("cp.async.commit_group;\n");
    }

    float  m   = -INFINITY;
    float  l   = 0.f;
    float4 acc = make_float4(0.f, 0.f, 0.f, 0.f);

    // ---- unified pipeline: units 0..31 = K stages, 32..63 = V stages -------
    // Invariant per iter u: wait_group 3 -> stage u arrived; barrier also
    // retires stage u-1 consumers; prefetch stage u+RING-1 into slot (u-1)%RING.
#pragma unroll 1
    for (int u = 0; u < 2 * NSTAGE; u++) {
        asm volatile("cp.async.wait_group %0;\n" :: "n"(RING - 2));
        __syncthreads();

        {   // prefetch next stage into the slot freed by stage u-1
            const int nu = u + RING - 1;
            float* slot = s_ring + (size_t)(nu % RING) * STAGEF;
            if (nu < NSTAGE)
                prefetch_stage(slot, nu, tbase, tid, last, s_bt, kcache, kfresh);
            else if (nu < 2 * NSTAGE)
                prefetch_stage(slot, nu - NSTAGE, tbase, tid, last, s_bt, vcache, vfresh);
            asm volatile("cp.async.commit_group;\n");   // empty group past end
        }

        const float* buf = s_ring + (size_t)(u % RING) * STAGEF;
        if (u < NSTAGE) {
            // ---- K stage u: warp w scores its head for 2 tokens -----------
#pragma unroll
            for (int i = 0; i < STAGE_T; i++) {
                const float4 kv = reinterpret_cast<const float4*>(
                    buf + (size_t)i * TOKF + (size_t)w * HDIM)[lane];
                float sc = kv.x * q4.x + kv.y * q4.y + kv.z * q4.z + kv.w * q4.w;
                sc = warp_sum(sc);
                const int lt = u * STAGE_T + i;
                const float sv = (tbase + lt < ctx) ? sc : -INFINITY;
                m = fmaxf(m, sv);          // warp-uniform
                if (lane == i) s_scores[w][lt] = sv;
            }
        } else {
            if (u == NSTAGE) {
                // ---- per-warp softmax at the K->V boundary ----------------
                // (block barrier above made all K-stage stores visible)
                const float msafe = (m == -INFINITY) ? 0.0f : m;
                const float e0 = __expf(s_scores[w][lane]      - msafe);
                const float e1 = __expf(s_scores[w][lane + 32] - msafe);
                s_scores[w][lane]      = e0;
                s_scores[w][lane + 32] = e1;
                l = warp_sum(e0 + e1);
                __syncwarp();
            }
            // ---- V stage u-32 ----------------------------------------------
            const int s = u - NSTAGE;
#pragma unroll
            for (int i = 0; i < STAGE_T; i++) {
                const int lt = s * STAGE_T + i;
                const float p = s_scores[w][lt];
                const float4 vv = reinterpret_cast<const float4*>(
                    buf + (size_t)i * TOKF + (size_t)w * HDIM)[lane];
                acc.x += p * vv.x;
                acc.y += p * vv.y;
                acc.z += p * vv.z;
                acc.w += p * vv.w;
            }
        }
    }

    // ---- per-warp partial write (no cross-warp merge needed) ---------------
    const int ps = (b * HEADS + w) * NSPLIT + split;
    reinterpret_cast<float4*>(g_part_o)[(size_t)ps * (HDIM / 4) + lane] = acc;
    if (lane == 0) { g_part_m[ps] = m; g_part_l[ps] = l; }

    // ---- last CTA of batch b combines all heads x splits -------------------
    __threadfence();
    __syncthreads();
    if (tid == 0)
        s_last = atomicAdd(&g_cnt[b], 1u);
    __syncthreads();
    if (s_last != NSPLIT - 1) return;
    __threadfence();

#pragma unroll
    for (int j = 0; j < 4; j++) {
        const int o  = j * THREADS + tid;    // 0..1023: head*128 + dim
        const int hh = o >> 7;
        const int d  = o & 127;
        const int base = (b * HEADS + hh) * NSPLIT;
        float Mg = -INFINITY;
#pragma unroll 1
        for (int i = 0; i < NSPLIT; i++)
            Mg = fmaxf(Mg, g_part_m[base + i]);
        float Lg = 0.f, r = 0.f;
#pragma unroll 1
        for (int i = 0; i < NSPLIT; i++) {
            const float mi = g_part_m[base + i];
            const float coef = (mi == -INFINITY) ? 0.f : __expf(mi - Mg);
            Lg += coef * g_part_l[base + i];
            r  += coef * g_part_o[(size_t)(base + i) * HDIM + d];
        }
        out[(size_t)(b * HEADS + hh) * HDIM + d] = r / Lg;
    }
    if (tid == 0) g_cnt[b] = 0;   // reset for next graph replay
}

extern "C" void kernel_launch(void* const* d_in, const int* in_sizes, int n_in,
                              void* d_out, int out_size)
{
    const float* q            = (const float*)d_in[0];
    const float* k            = (const float*)d_in[1];
    const float* v            = (const float*)d_in[2];
    const float* k_cache      = (const float*)d_in[3];
    const float* v_cache      = (const float*)d_in[4];
    // d_in[5] = slot_mapping (unused: substitution at t == ctx-1 is equivalent)
    const int*   block_tables = (const int*)d_in[6];
    const int*   context_lens = (const int*)d_in[7];
    float*       out          = (float*)d_out;

    const size_t shmem = (size_t)RING * STAGEF * sizeof(float);   // 40KB
    paged_attn_split_kernel<<<BATCH * NSPLIT, THREADS, shmem>>>(
        q, k, v, k_cache, v_cache, block_tables, context_lens, out);
}

// round 16
// speedup vs baseline: 1.5327x; 1.5327x over previous
#include <cuda_runtime.h>
#include <math.h>

// Problem shape (fixed by the dataset instance)
#define BATCH 16
#define HEADS 8
#define HDIM  128
#define BSIZE 16               // tokens per cache block
#define BPS   128              // blocks per sequence
#define TMAX  (BSIZE * BPS)    // 2048 tokens
#define NSPLIT 16
#define TSPLIT (TMAX / NSPLIT)     // 128 tokens per split
#define BLKSPLIT (TSPLIT / BSIZE)  // 8 cache blocks per split
#define THREADS 128
#define NWARPS  (THREADS / 32)     // 4
#define TPW     (TSPLIT / NWARPS)  // 32 tokens per warp
#define DEPTH   4                  // tokens per in-flight load batch

// split-KV partials + completion counters (allocation-free scratch, zero-init)
__device__ float g_part_o[BATCH * HEADS * NSPLIT * HDIM];
__device__ float g_part_m[BATCH * HEADS * NSPLIT];
__device__ float g_part_l[BATCH * HEADS * NSPLIT];
__device__ unsigned int g_cnt[BATCH * HEADS];

__device__ __forceinline__ float warp_sum(float v) {
#pragma unroll
    for (int o = 16; o > 0; o >>= 1) v += __shfl_xor_sync(0xffffffffu, v, o);
    return v;
}
__device__ __forceinline__ float warp_max(float v) {
#pragma unroll
    for (int o = 16; o > 0; o >>= 1) v = fmaxf(v, __shfl_xor_sync(0xffffffffu, v, o));
    return v;
}

__global__ __launch_bounds__(THREADS, 10)
void paged_attn_split_kernel(const float* __restrict__ q,
                             const float* __restrict__ knew,
                             const float* __restrict__ vnew,
                             const float* __restrict__ kcache,
                             const float* __restrict__ vcache,
                             const int*   __restrict__ block_tables,
                             const int*   __restrict__ context_lens,
                             float*       __restrict__ out)
{
    const float SCALE = 0.08838834764831845f;

    // Grid layout: adjacent CTAs = the 8 heads of the same (b, split) chunk.
    const int idx   = blockIdx.x;
    const int h     = idx % HEADS;
    const int bs_   = idx / HEADS;
    const int split = bs_ % NSPLIT;
    const int b     = bs_ / NSPLIT;
    const int bh    = b * HEADS + h;

    const int tid   = threadIdx.x;
    const int lane  = tid & 31;
    const int w     = tid >> 5;
    const int tbase = split * TSPLIT;

    __shared__ float s_scores[TSPLIT];
    __shared__ int   s_bt[BLKSPLIT];
    __shared__ float s_m[NWARPS];
    __shared__ float s_l[NWARPS];
    __shared__ float s_acc[NWARPS][HDIM];
    __shared__ unsigned int s_last;

    if (tid < BLKSPLIT)
        s_bt[tid] = block_tables[b * BPS + split * BLKSPLIT + tid];

    const int ctx  = context_lens[b];
    const int last = ctx - 1;

    float4 q4 = reinterpret_cast<const float4*>(q + (size_t)bh * HDIM)[lane];
    q4.x *= SCALE; q4.y *= SCALE; q4.z *= SCALE; q4.w *= SCALE;

    const float* kfresh = knew + (size_t)bh * HDIM;
    const float* vfresh = vnew + (size_t)bh * HDIM;

    __syncthreads();

    // ------------- Phase 1: scores (4-deep load batches per warp) ----------
    const int lbeg = w * TPW;
#pragma unroll 1
    for (int l0 = lbeg; l0 < lbeg + TPW; l0 += DEPTH) {
        float4 kv[DEPTH];
#pragma unroll
        for (int i = 0; i < DEPTH; i++) {
            const int lt = l0 + i;                 // local token in split
            const int t  = tbase + lt;             // global token
            const int blk = s_bt[lt >> 4];
            const size_t row = ((size_t)blk * BSIZE + (t & (BSIZE - 1))) * HEADS + h;
            kv[i] = (t == last)
                  ? reinterpret_cast<const float4*>(kfresh)[lane]
                  : __ldcs(reinterpret_cast<const float4*>(kcache + row * HDIM) + lane);
        }
#pragma unroll
        for (int i = 0; i < DEPTH; i++) {
            float s = kv[i].x * q4.x + kv[i].y * q4.y + kv[i].z * q4.z + kv[i].w * q4.w;
            s = warp_sum(s);
            if (lane == i) {
                const int lt = l0 + i;
                s_scores[lt] = (tbase + lt < ctx) ? s : -INFINITY;
            }
        }
    }
    __syncwarp();

    // ------------- Phase 2: per-warp softmax (1 score per lane) ------------
    const float s0 = s_scores[lbeg + lane];
    const float m  = warp_max(s0);
    const float msafe = (m == -INFINITY) ? 0.0f : m;
    const float e0 = __expf(s0 - msafe);
    s_scores[lbeg + lane] = e0;
    const float l = warp_sum(e0);
    __syncwarp();

    // ------------- Phase 3: unnormalized o = sum p_t v_t -------------------
    float4 acc = make_float4(0.f, 0.f, 0.f, 0.f);
#pragma unroll 1
    for (int l0 = lbeg; l0 < lbeg + TPW; l0 += DEPTH) {
        float4 vv[DEPTH];
        float  p[DEPTH];
#pragma unroll
        for (int i = 0; i < DEPTH; i++) {
            const int lt = l0 + i;
            const int t  = tbase + lt;
            const int blk = s_bt[lt >> 4];
            const size_t row = ((size_t)blk * BSIZE + (t & (BSIZE - 1))) * HEADS + h;
            vv[i] = (t == last)
                  ? reinterpret_cast<const float4*>(vfresh)[lane]
                  : __ldcs(reinterpret_cast<const float4*>(vcache + row * HDIM) + lane);
            p[i]  = s_scores[lt];                   // LDS broadcast
        }
#pragma unroll
        for (int i = 0; i < DEPTH; i++) {
            acc.x += p[i] * vv[i].x;
            acc.y += p[i] * vv[i].y;
            acc.z += p[i] * vv[i].z;
            acc.w += p[i] * vv[i].w;
        }
    }

    // ------------- cross-warp merge -> split partial ------------------------
    if (lane == 0) { s_m[w] = m; s_l[w] = l; }
    reinterpret_cast<float4*>(s_acc[w])[lane] = acc;
    __syncthreads();

    float M = -INFINITY;
#pragma unroll
    for (int ww = 0; ww < NWARPS; ww++) M = fmaxf(M, s_m[ww]);

    const int ps = bh * NSPLIT + split;
    if (tid < HDIM) {
        float r = 0.f;
#pragma unroll
        for (int ww = 0; ww < NWARPS; ww++) {
            const float coef = (s_m[ww] == -INFINITY) ? 0.f : __expf(s_m[ww] - M);
            r += coef * s_acc[ww][tid];
        }
        g_part_o[(size_t)ps * HDIM + tid] = r;
    }
    if (tid == 0) {
        float L = 0.f;
#pragma unroll
        for (int ww = 0; ww < NWARPS; ww++) {
            const float coef = (s_m[ww] == -INFINITY) ? 0.f : __expf(s_m[ww] - M);
            L += coef * s_l[ww];
        }
        g_part_m[ps] = M;
        g_part_l[ps] = L;
    }

    // ------------- last CTA per (b,h) combines (fused, no 2nd launch) ------
    __threadfence();
    __syncthreads();
    if (tid == 0)
        s_last = atomicAdd(&g_cnt[bh], 1u);
    __syncthreads();
    if (s_last != NSPLIT - 1) return;
    __threadfence();

    if (tid < HDIM) {
        float Mg = -INFINITY;
#pragma unroll 1
        for (int i = 0; i < NSPLIT; i++)
            Mg = fmaxf(Mg, g_part_m[bh * NSPLIT + i]);
        float Lg = 0.f, r = 0.f;
#pragma unroll 1
        for (int i = 0; i < NSPLIT; i++) {
            const float mi = g_part_m[bh * NSPLIT + i];
            const float coef = (mi == -INFINITY) ? 0.f : __expf(mi - Mg);
            Lg += coef * g_part_l[bh * NSPLIT + i];
            r  += coef * g_part_o[((size_t)bh * NSPLIT + i) * HDIM + tid];
        }
        out[(size_t)bh * HDIM + tid] = r / Lg;
    }
    if (tid == 0) g_cnt[bh] = 0;   // reset for next graph replay
}

extern "C" void kernel_launch(void* const* d_in, const int* in_sizes, int n_in,
                              void* d_out, int out_size)
{
    const float* q            = (const float*)d_in[0];
    const float* k            = (const float*)d_in[1];
    const float* v            = (const float*)d_in[2];
    const float* k_cache      = (const float*)d_in[3];
    const float* v_cache      = (const float*)d_in[4];
    // d_in[5] = slot_mapping (unused: substitution at t == ctx-1 is equivalent)
    const int*   block_tables = (const int*)d_in[6];
    const int*   context_lens = (const int*)d_in[7];
    float*       out          = (float*)d_out;

    paged_attn_split_kernel<<<BATCH * HEADS * NSPLIT, THREADS>>>(
        q, k, v, k_cache, v_cache, block_tables, context_lens, out);
}